// round 8
// baseline (speedup 1.0000x reference)
#include <cuda_runtime.h>
#include <cstdint>

// Haar IDWT (reference's LH-uses-LPF-twice quirk folded into LL by linearity).
//
//   out[n,a,b] = 0.5 * ((ll+lh) + sb*hl + sa*sb*hh)
//   sa = (a even ? -1 : +1), sb = (b even ? -1 : +1)
//   (ll,lh,hl,hh) = in[n, a>>1, b>>1, 0..3]   (contiguous float4, channels-last)
//
// R8 = R1 data layout (best: dense 512B load/store instructions, 2 px/thread)
// restructured as a PERSISTENT grid: 1184 CTAs (148 SMs x 8), grid-stride
// x2-unrolled loop -> one wave, no wave-transition stalls, 4 loads in flight.

namespace {
constexpr int B = 16;
constexpr int H = 512;
constexpr int W = 512;
constexpr int PAIRS = B * H * (W / 2);   // 2,097,152 work items (pixel pairs)
constexpr int OW4 = (2 * W) / 4;         // 256 float4 per output row
constexpr int NBLK = 148 * 8;            // persistent grid: one wave
constexpr int NTHR = NBLK * 256;         // 303,104 threads
}

__global__ void __launch_bounds__(256) idwt_haar_kernel(
    const float4* __restrict__ in, float4* __restrict__ out)
{
    int tid = blockIdx.x * 256 + threadIdx.x;

    // x2-unrolled grid-stride: front-batch two pairs' loads (MLP_p1 = 4)
    for (int idx = tid; idx < PAIRS; idx += 2 * NTHR) {
        int idx2 = idx + NTHR;
        bool has2 = idx2 < PAIRS;

        int cA = idx & 255, rA = (idx >> 8) & (H - 1), nA = idx >> 17;
        const float4* pA = in + (((size_t)nA * H + rA) << 9) + 2 * cA;
        float4 a0 = pA[0];
        float4 a1 = pA[1];

        int cB = idx2 & 255, rB = (idx2 >> 8) & (H - 1), nB = idx2 >> 17;
        const float4* pB = in + (((size_t)nB * H + rB) << 9) + 2 * cB;
        float4 b0, b1;
        if (has2) { b0 = pB[0]; b1 = pB[1]; }

        // ---- pair A ----
        {
            float e0  = 0.5f * (a0.x + a0.y), hl0 = 0.5f * a0.z, hh0 = 0.5f * a0.w;
            float e1  = 0.5f * (a1.x + a1.y), hl1 = 0.5f * a1.z, hh1 = 0.5f * a1.w;
            float4 top, bot;
            top.x = e0 - hl0 + hh0;  top.y = e0 + hl0 - hh0;
            top.z = e1 - hl1 + hh1;  top.w = e1 + hl1 - hh1;
            bot.x = e0 - hl0 - hh0;  bot.y = e0 + hl0 + hh0;
            bot.z = e1 - hl1 - hh1;  bot.w = e1 + hl1 + hh1;
            size_t o4 = (((size_t)nA << 10) + 2 * rA) * OW4 + cA;
            out[o4]       = top;
            out[o4 + OW4] = bot;
        }
        // ---- pair B ----
        if (has2) {
            float e0  = 0.5f * (b0.x + b0.y), hl0 = 0.5f * b0.z, hh0 = 0.5f * b0.w;
            float e1  = 0.5f * (b1.x + b1.y), hl1 = 0.5f * b1.z, hh1 = 0.5f * b1.w;
            float4 top, bot;
            top.x = e0 - hl0 + hh0;  top.y = e0 + hl0 - hh0;
            top.z = e1 - hl1 + hh1;  top.w = e1 + hl1 - hh1;
            bot.x = e0 - hl0 - hh0;  bot.y = e0 + hl0 + hh0;
            bot.z = e1 - hl1 - hh1;  bot.w = e1 + hl1 + hh1;
            size_t o4 = (((size_t)nB << 10) + 2 * rB) * OW4 + cB;
            out[o4]       = top;
            out[o4 + OW4] = bot;
        }
    }
}

extern "C" void kernel_launch(void* const* d_in, const int* in_sizes, int n_in,
                              void* d_out, int out_size)
{
    const float4* in = (const float4*)d_in[0];
    float4* out = (float4*)d_out;
    idwt_haar_kernel<<<NBLK, 256>>>(in, out);
}

// round 9
// speedup vs baseline: 1.0070x; 1.0070x over previous
#include <cuda_runtime.h>
#include <cstdint>

// Haar IDWT (reference's LH-uses-LPF-twice quirk folded into LL by linearity).
//
//   out[n,a,b] = 0.5 * ((ll+lh) + sb*hl + sa*sb*hh)
//   sa = (a even ? -1 : +1), sb = (b even ? -1 : +1)
//   (ll,lh,hl,hh) = in[n, a>>1, b>>1, 0..3]   (contiguous float4, channels-last)
//
// FINAL (converged over 8 rounds): 2 input pixels/thread, every load and
// store a dense 512B-per-warp float4 instruction. Moves the compulsory
// 134 MB (67 in + 67 out) at 7.6 TB/s in-kernel = 95% of HBM spec.
// Falsified alternatives: higher MLP mappings, .cs hints, shfl STG.128,
// persistent grid — all matched or regressed (see round journal).

namespace {
constexpr int B = 16;
constexpr int H = 512;
constexpr int W = 512;
constexpr int PAIRS_PER_ROW = W / 2;                 // 256
constexpr int TOTAL = B * H * PAIRS_PER_ROW;         // 2,097,152 threads
constexpr int OW = 2 * W;                            // 1024 output width (floats)
}

__global__ void __launch_bounds__(256) idwt_haar_kernel(
    const float4* __restrict__ in, float4* __restrict__ out)
{
    int idx = blockIdx.x * blockDim.x + threadIdx.x;
    if (idx >= TOTAL) return;

    int c = idx & (PAIRS_PER_ROW - 1);       // pair index 0..255
    int r = (idx >> 8) & (H - 1);            // input row 0..511
    int n = idx >> 17;                       // batch 0..15

    const float4* rowp = in + ((size_t)n * H + r) * W;
    float4 p0 = rowp[2 * c];
    float4 p1 = rowp[2 * c + 1];

    // halved components
    float e0  = 0.5f * (p0.x + p0.y);
    float hl0 = 0.5f * p0.z;
    float hh0 = 0.5f * p0.w;
    float e1  = 0.5f * (p1.x + p1.y);
    float hl1 = 0.5f * p1.z;
    float hh1 = 0.5f * p1.w;

    // top row (a = 2r, even -> sa = -1); cols: even b -> sb=-1, odd b -> sb=+1
    float4 top, bot;
    top.x = e0 - hl0 + hh0;   // (2r,   4c  )  b even
    top.y = e0 + hl0 - hh0;   // (2r,   4c+1)  b odd
    top.z = e1 - hl1 + hh1;   // (2r,   4c+2)
    top.w = e1 + hl1 - hh1;   // (2r,   4c+3)
    // bottom row (a = 2r+1, odd -> sa = +1)
    bot.x = e0 - hl0 - hh0;   // (2r+1, 4c  )
    bot.y = e0 + hl0 + hh0;   // (2r+1, 4c+1)
    bot.z = e1 - hl1 - hh1;   // (2r+1, 4c+2)
    bot.w = e1 + hl1 + hh1;   // (2r+1, 4c+3)

    // output float4 index: ((n*1024 + 2r)*1024 + 4c) / 4
    size_t o4 = ((size_t)n * 1024 + 2 * r) * (OW / 4) + c;
    out[o4]            = top;
    out[o4 + OW / 4]   = bot;   // next output row (+1024 floats = +256 float4)
}

extern "C" void kernel_launch(void* const* d_in, const int* in_sizes, int n_in,
                              void* d_out, int out_size)
{
    const float4* in = (const float4*)d_in[0];
    float4* out = (float4*)d_out;
    dim3 block(256);
    dim3 grid((TOTAL + 255) / 256);
    idwt_haar_kernel<<<grid, block>>>(in, out);
}

// round 10
// speedup vs baseline: 1.0780x; 1.0705x over previous
#include <cuda_runtime.h>
#include <cstdint>

// Haar IDWT (reference's LH-uses-LPF-twice quirk folded into LL by linearity).
//
//   out[n,a,b] = 0.5 * ((ll+lh) + sb*hl + sa*sb*hh)
//   sa = (a even ? -1 : +1), sb = (b even ? -1 : +1)
//   (ll,lh,hl,hh) = in[n, a>>1, b>>1, 0..3]   (contiguous float4, channels-last)
//
// CONVERGED FINAL: 2 input pixels/thread; every load and store is a dense
// 512B-per-warp float4 instruction. ncu-stable at 17.6us = 134 MB compulsory
// traffic at 7.6 TB/s (95% of HBM spec). Wall variance on identical source
// measured at +/-2us (R6 vs R9); all structural alternatives (MLP 4, .cs
// hints, shfl STG.128, persistent grid) gave identical ncu durations.

namespace {
constexpr int B = 16;
constexpr int H = 512;
constexpr int W = 512;
constexpr int PAIRS_PER_ROW = W / 2;                 // 256
constexpr int TOTAL = B * H * PAIRS_PER_ROW;         // 2,097,152 threads
constexpr int OW = 2 * W;                            // 1024 output width (floats)
}

__global__ void __launch_bounds__(256) idwt_haar_kernel(
    const float4* __restrict__ in, float4* __restrict__ out)
{
    int idx = blockIdx.x * blockDim.x + threadIdx.x;
    if (idx >= TOTAL) return;

    int c = idx & (PAIRS_PER_ROW - 1);       // pair index 0..255
    int r = (idx >> 8) & (H - 1);            // input row 0..511
    int n = idx >> 17;                       // batch 0..15

    const float4* rowp = in + ((size_t)n * H + r) * W;
    float4 p0 = rowp[2 * c];
    float4 p1 = rowp[2 * c + 1];

    // halved components
    float e0  = 0.5f * (p0.x + p0.y);
    float hl0 = 0.5f * p0.z;
    float hh0 = 0.5f * p0.w;
    float e1  = 0.5f * (p1.x + p1.y);
    float hl1 = 0.5f * p1.z;
    float hh1 = 0.5f * p1.w;

    // top row (a = 2r, even -> sa = -1); cols: even b -> sb=-1, odd b -> sb=+1
    float4 top, bot;
    top.x = e0 - hl0 + hh0;   // (2r,   4c  )  b even
    top.y = e0 + hl0 - hh0;   // (2r,   4c+1)  b odd
    top.z = e1 - hl1 + hh1;   // (2r,   4c+2)
    top.w = e1 + hl1 - hh1;   // (2r,   4c+3)
    // bottom row (a = 2r+1, odd -> sa = +1)
    bot.x = e0 - hl0 - hh0;   // (2r+1, 4c  )
    bot.y = e0 + hl0 + hh0;   // (2r+1, 4c+1)
    bot.z = e1 - hl1 - hh1;   // (2r+1, 4c+2)
    bot.w = e1 + hl1 + hh1;   // (2r+1, 4c+3)

    // output float4 index: ((n*1024 + 2r)*1024 + 4c) / 4
    size_t o4 = ((size_t)n * 1024 + 2 * r) * (OW / 4) + c;
    out[o4]            = top;
    out[o4 + OW / 4]   = bot;   // next output row (+1024 floats = +256 float4)
}

extern "C" void kernel_launch(void* const* d_in, const int* in_sizes, int n_in,
                              void* d_out, int out_size)
{
    const float4* in = (const float4*)d_in[0];
    float4* out = (float4*)d_out;
    dim3 block(256);
    dim3 grid((TOTAL + 255) / 256);
    idwt_haar_kernel<<<grid, block>>>(in, out);
}